// round 7
// baseline (speedup 1.0000x reference)
#include <cuda_runtime.h>
#include <math.h>
#include <stdint.h>

#define BATCH 4
#define SEQ   4096
#define EMB   1024
#define HD    128
#define MTOT  (BATCH * SEQ)

// Scratch for projected q, k, v (fp32), allocation-free device globals
__device__ float g_q[(size_t)MTOT * HD];
__device__ float g_k[(size_t)MTOT * HD];
__device__ float g_v[(size_t)MTOT * HD];

// ---------------------------------------------------------------------------
// tf32 helpers
// ---------------------------------------------------------------------------
__device__ __forceinline__ uint32_t f2tf(float f) {
    uint32_t u;
    asm("cvt.rna.tf32.f32 %0, %1;" : "=r"(u) : "f"(f));
    return u;
}

// D += A(16x8, tf32, row) * B(8x8, tf32, col); accumulate in place.
__device__ __forceinline__ void mma8(float* d, const uint32_t* a, const uint32_t* b) {
    asm volatile(
        "mma.sync.aligned.m16n8k8.row.col.f32.tf32.tf32.f32 "
        "{%0,%1,%2,%3}, {%4,%5,%6,%7}, {%8,%9}, {%0,%1,%2,%3};\n"
        : "+f"(d[0]), "+f"(d[1]), "+f"(d[2]), "+f"(d[3])
        : "r"(a[0]), "r"(a[1]), "r"(a[2]), "r"(a[3]), "r"(b[0]), "r"(b[1]));
}

// ---------------------------------------------------------------------------
// Kernel 1: QKV projection, out[which] = x[M,E] @ W[E,H], tf32 MMA.
// CTA tile 128(M) x 128(N=HD), BK=32. 8 warps: warp tile 32x64.
// ---------------------------------------------------------------------------
#define XSTR 36     // 36 % 32 == 4  -> A-frag loads conflict-free
#define WSTR 136    // 136 % 32 == 8 -> B-frag loads conflict-free

__global__ __launch_bounds__(256) void qkv_kernel(
    const float* __restrict__ x,
    const float* __restrict__ Wq,
    const float* __restrict__ Wk,
    const float* __restrict__ Wv)
{
    const int which = blockIdx.y;
    const float* __restrict__ W = (which == 0) ? Wq : (which == 1) ? Wk : Wv;
    float* __restrict__ out = (which == 0) ? g_q : (which == 1) ? g_k : g_v;

    __shared__ uint32_t Xs[128 * XSTR];
    __shared__ uint32_t Ws[32 * WSTR];

    const int tid  = threadIdx.x;
    const int warp = tid >> 5;
    const int lane = tid & 31;
    const int g = lane >> 2;
    const int t = lane & 3;
    const int wm = warp & 3;        // 4 M bands of 32
    const int wn = warp >> 2;       // 2 N halves of 64
    const int m0 = wm * 32;
    const int n0 = wn * 64;
    const int row_base = blockIdx.x * 128;

    float acc[2][8][4];
#pragma unroll
    for (int i = 0; i < 2; i++)
#pragma unroll
        for (int j = 0; j < 8; j++)
#pragma unroll
            for (int r = 0; r < 4; r++) acc[i][j][r] = 0.f;

    for (int k0 = 0; k0 < EMB; k0 += 32) {
        // stage X tile 128x32 (1024 float4, 4/thread)
#pragma unroll
        for (int it = 0; it < 4; it++) {
            int idx = tid + it * 256;
            int r = idx >> 3;
            int c = (idx & 7) * 4;
            float4 v = *(const float4*)&x[(size_t)(row_base + r) * EMB + k0 + c];
            uint4 u = make_uint4(f2tf(v.x), f2tf(v.y), f2tf(v.z), f2tf(v.w));
            *(uint4*)&Xs[r * XSTR + c] = u;
        }
        // stage W tile 32x128 (1024 float4, 4/thread)
#pragma unroll
        for (int it = 0; it < 4; it++) {
            int idx = tid + it * 256;
            int r = idx >> 5;
            int c = (idx & 31) * 4;
            float4 v = *(const float4*)&W[(size_t)(k0 + r) * HD + c];
            uint4 u = make_uint4(f2tf(v.x), f2tf(v.y), f2tf(v.z), f2tf(v.w));
            *(uint4*)&Ws[r * WSTR + c] = u;
        }
        __syncthreads();

#pragma unroll
        for (int ks = 0; ks < 4; ks++) {
            const int kk = ks * 8;
            uint32_t a[2][4];
#pragma unroll
            for (int i = 0; i < 2; i++) {
                int ab = (m0 + i * 16 + g) * XSTR + kk + t;
                a[i][0] = Xs[ab];
                a[i][1] = Xs[ab + 8 * XSTR];
                a[i][2] = Xs[ab + 4];
                a[i][3] = Xs[ab + 8 * XSTR + 4];
            }
#pragma unroll
            for (int j = 0; j < 8; j++) {
                int bb = (kk + t) * WSTR + n0 + j * 8 + g;
                uint32_t b[2] = { Ws[bb], Ws[bb + 4 * WSTR] };
                mma8(acc[0][j], a[0], b);
                mma8(acc[1][j], a[1], b);
            }
        }
        __syncthreads();
    }

#pragma unroll
    for (int i = 0; i < 2; i++)
#pragma unroll
        for (int j = 0; j < 8; j++) {
            int row = row_base + m0 + i * 16 + g;
            int col = n0 + j * 8 + 2 * t;
            *(float2*)&out[(size_t)row * HD + col] =
                make_float2(acc[i][j][0], acc[i][j][1]);
            *(float2*)&out[(size_t)(row + 8) * HD + col] =
                make_float2(acc[i][j][2], acc[i][j][3]);
        }
}

// ---------------------------------------------------------------------------
// Kernel 2: causal flash attention, tf32 MMA.
// BM=64 queries, BN=64 keys per iter. 8 warps: warp w owns m16 tile (w&3),
// n-half (w>>2). Softmax stats in registers + small smem exchange per iter.
// ---------------------------------------------------------------------------
#define QKSTR 132   // 132 % 32 == 4 (A-pattern rows: Q, K)
#define VSTR  136   // 136 % 32 == 8 (B-pattern rows: V)
#define PSTR  68    // 68  % 32 == 4 (A-pattern rows: P)

#define ATTN_SMEM_U32 (2 * 64 * QKSTR + 64 * VSTR + 64 * PSTR + 4 * 64)
#define ATTN_SMEM_BYTES (ATTN_SMEM_U32 * 4)

__global__ __launch_bounds__(256) void attn_kernel(float* __restrict__ out)
{
    const int batch = blockIdx.y;
    const int qt = (int)(gridDim.x - 1) - (int)blockIdx.x;   // heavy tiles first
    const int q_base = qt * 64;
    const size_t boff = (size_t)batch * SEQ * HD;

    extern __shared__ uint32_t sm[];
    uint32_t* Qs = sm;                      // 64 x 132
    uint32_t* Ks = Qs + 64 * QKSTR;         // 64 x 132
    uint32_t* Vs = Ks + 64 * QKSTR;         // 64 x 136
    uint32_t* Ps = Vs + 64 * VSTR;          // 64 x 68
    float* redmax = (float*)(Ps + 64 * PSTR);   // [2][64]
    float* redsum = redmax + 2 * 64;            // [2][64]

    const int tid  = threadIdx.x;
    const int warp = tid >> 5;
    const int lane = tid & 31;
    const int g = lane >> 2;
    const int t = lane & 3;
    const int mt = warp & 3;        // m16 tile index
    const int nh = warp >> 2;       // n / hd half
    const int m0 = mt * 16;
    const int nb = nh * 32;         // key-col base for S
    const int hb = nh * 64;         // hd-col base for O
    const int r0l = m0 + g;         // local rows this thread owns
    const int r1l = m0 + g + 8;

    const float qscale = rsqrtf((float)HD);

    // stage Q (scaled, tf32): 64x128 = 2048 float4, 8 per thread
#pragma unroll
    for (int it = 0; it < 8; it++) {
        int idx = tid + it * 256;
        int r = idx >> 5;
        int c = (idx & 31) * 4;
        float4 v = *(const float4*)&g_q[boff + (size_t)(q_base + r) * HD + c];
        uint4 u = make_uint4(f2tf(v.x * qscale), f2tf(v.y * qscale),
                             f2tf(v.z * qscale), f2tf(v.w * qscale));
        *(uint4*)&Qs[r * QKSTR + c] = u;
    }

    float o[8][4];
#pragma unroll
    for (int j = 0; j < 8; j++)
#pragma unroll
        for (int r = 0; r < 4; r++) o[j][r] = 0.f;

    float m_i0 = -1e30f, m_i1 = -1e30f;
    float l_i0 = 0.f,    l_i1 = 0.f;

    for (int kt = 0; kt <= qt; kt++) {
        __syncthreads();    // prior iter's PV reads / Q staging visible

        // stage K, V tiles (tf32): 2 x 2048 float4, 16 per thread
        const int k_base = kt * 64;
#pragma unroll
        for (int it = 0; it < 8; it++) {
            int idx = tid + it * 256;
            int r = idx >> 5;
            int c = (idx & 31) * 4;
            float4 kv = *(const float4*)&g_k[boff + (size_t)(k_base + r) * HD + c];
            *(uint4*)&Ks[r * QKSTR + c] =
                make_uint4(f2tf(kv.x), f2tf(kv.y), f2tf(kv.z), f2tf(kv.w));
            float4 vv = *(const float4*)&g_v[boff + (size_t)(k_base + r) * HD + c];
            *(uint4*)&Vs[r * VSTR + c] =
                make_uint4(f2tf(vv.x), f2tf(vv.y), f2tf(vv.z), f2tf(vv.w));
        }
        __syncthreads();

        // S = Q @ K^T  (warp: 1 m-tile x 4 n-tiles, k=128)
        float s[4][4];
#pragma unroll
        for (int j = 0; j < 4; j++)
#pragma unroll
            for (int r = 0; r < 4; r++) s[j][r] = 0.f;

#pragma unroll
        for (int ks = 0; ks < 16; ks++) {
            const int kk = ks * 8;
            uint32_t a[4];
            int ab = r0l * QKSTR + kk + t;
            a[0] = Qs[ab];
            a[1] = Qs[ab + 8 * QKSTR];
            a[2] = Qs[ab + 4];
            a[3] = Qs[ab + 8 * QKSTR + 4];
#pragma unroll
            for (int j = 0; j < 4; j++) {
                int bb = (nb + j * 8 + g) * QKSTR + kk + t;
                uint32_t b[2] = { Ks[bb], Ks[bb + 4] };
                mma8(s[j], a, b);
            }
        }

        // causal mask on diagonal tile
        if (kt == qt) {
#pragma unroll
            for (int j = 0; j < 4; j++) {
                int cn = nb + j * 8 + 2 * t;
                if (cn     > r0l) s[j][0] = -1e30f;
                if (cn + 1 > r0l) s[j][1] = -1e30f;
                if (cn     > r1l) s[j][2] = -1e30f;
                if (cn + 1 > r1l) s[j][3] = -1e30f;
            }
        }

        // per-half row max -> smem
        float mx0 = -1e30f, mx1 = -1e30f;
#pragma unroll
        for (int j = 0; j < 4; j++) {
            mx0 = fmaxf(mx0, fmaxf(s[j][0], s[j][1]));
            mx1 = fmaxf(mx1, fmaxf(s[j][2], s[j][3]));
        }
        mx0 = fmaxf(mx0, __shfl_xor_sync(0xffffffffu, mx0, 1));
        mx0 = fmaxf(mx0, __shfl_xor_sync(0xffffffffu, mx0, 2));
        mx1 = fmaxf(mx1, __shfl_xor_sync(0xffffffffu, mx1, 1));
        mx1 = fmaxf(mx1, __shfl_xor_sync(0xffffffffu, mx1, 2));
        if (t == 0) {
            redmax[nh * 64 + r0l] = mx0;
            redmax[nh * 64 + r1l] = mx1;
        }
        __syncthreads();

        const float m_new0 = fmaxf(m_i0, fmaxf(redmax[r0l], redmax[64 + r0l]));
        const float m_new1 = fmaxf(m_i1, fmaxf(redmax[r1l], redmax[64 + r1l]));

        // exp, P -> smem (tf32), per-half row sum -> smem
        float sum0 = 0.f, sum1 = 0.f;
#pragma unroll
        for (int j = 0; j < 4; j++) {
            float p00 = __expf(s[j][0] - m_new0);
            float p01 = __expf(s[j][1] - m_new0);
            float p10 = __expf(s[j][2] - m_new1);
            float p11 = __expf(s[j][3] - m_new1);
            sum0 += p00 + p01;
            sum1 += p10 + p11;
            int cn = nb + j * 8 + 2 * t;
            *(uint2*)&Ps[r0l * PSTR + cn] = make_uint2(f2tf(p00), f2tf(p01));
            *(uint2*)&Ps[r1l * PSTR + cn] = make_uint2(f2tf(p10), f2tf(p11));
        }
        sum0 += __shfl_xor_sync(0xffffffffu, sum0, 1);
        sum0 += __shfl_xor_sync(0xffffffffu, sum0, 2);
        sum1 += __shfl_xor_sync(0xffffffffu, sum1, 1);
        sum1 += __shfl_xor_sync(0xffffffffu, sum1, 2);
        if (t == 0) {
            redsum[nh * 64 + r0l] = sum0;
            redsum[nh * 64 + r1l] = sum1;
        }
        __syncthreads();

        const float corr0 = __expf(m_i0 - m_new0);
        const float corr1 = __expf(m_i1 - m_new1);
        l_i0 = l_i0 * corr0 + redsum[r0l] + redsum[64 + r0l];
        l_i1 = l_i1 * corr1 + redsum[r1l] + redsum[64 + r1l];
        m_i0 = m_new0;
        m_i1 = m_new1;

        // rescale O, then O += P @ V
#pragma unroll
        for (int j = 0; j < 8; j++) {
            o[j][0] *= corr0; o[j][1] *= corr0;
            o[j][2] *= corr1; o[j][3] *= corr1;
        }
#pragma unroll
        for (int ks = 0; ks < 8; ks++) {
            const int kk = ks * 8;
            uint32_t a[4];
            int ab = r0l * PSTR + kk + t;
            a[0] = Ps[ab];
            a[1] = Ps[ab + 8 * PSTR];
            a[2] = Ps[ab + 4];
            a[3] = Ps[ab + 8 * PSTR + 4];
#pragma unroll
            for (int j = 0; j < 8; j++) {
                int bb = (kk + t) * VSTR + hb + j * 8 + g;
                uint32_t b[2] = { Vs[bb], Vs[bb + 4 * VSTR] };
                mma8(o[j], a, b);
            }
        }
    }

    // normalize and write
    const float inv0 = 1.f / l_i0;
    const float inv1 = 1.f / l_i1;
#pragma unroll
    for (int j = 0; j < 8; j++) {
        int col = hb + j * 8 + 2 * t;
        int row = q_base + r0l;
        *(float2*)&out[boff + (size_t)row * HD + col] =
            make_float2(o[j][0] * inv0, o[j][1] * inv0);
        *(float2*)&out[boff + (size_t)(row + 8) * HD + col] =
            make_float2(o[j][2] * inv1, o[j][3] * inv1);
    }
}

// ---------------------------------------------------------------------------
extern "C" void kernel_launch(void* const* d_in, const int* in_sizes, int n_in,
                              void* d_out, int out_size)
{
    const float* x  = (const float*)d_in[0];
    const float* Wq = (const float*)d_in[1];
    const float* Wk = (const float*)d_in[2];
    const float* Wv = (const float*)d_in[3];
    float* out = (float*)d_out;

    cudaFuncSetAttribute(attn_kernel,
                         cudaFuncAttributeMaxDynamicSharedMemorySize,
                         ATTN_SMEM_BYTES);

    qkv_kernel<<<dim3(MTOT / 128, 3), 256>>>(x, Wq, Wk, Wv);
    attn_kernel<<<dim3(SEQ / 64, BATCH), 256, ATTN_SMEM_BYTES>>>(out);
}

// round 8
// speedup vs baseline: 1.0108x; 1.0108x over previous
#include <cuda_runtime.h>
#include <math.h>
#include <stdint.h>

#define BATCH 4
#define SEQ   4096
#define EMB   1024
#define HD    128
#define MTOT  (BATCH * SEQ)

// Scratch for projected q, k, v (fp32), allocation-free device globals
__device__ float g_q[(size_t)MTOT * HD];
__device__ float g_k[(size_t)MTOT * HD];
__device__ float g_v[(size_t)MTOT * HD];

// ---------------------------------------------------------------------------
// tf32 helpers
// ---------------------------------------------------------------------------
__device__ __forceinline__ uint32_t f2tf(float f) {
    uint32_t u;
    asm("cvt.rna.tf32.f32 %0, %1;" : "=r"(u) : "f"(f));
    return u;
}

// D += A(16x8, tf32, row) * B(8x8, tf32, col); accumulate in place.
__device__ __forceinline__ void mma8(float* d, const uint32_t* a, const uint32_t* b) {
    asm volatile(
        "mma.sync.aligned.m16n8k8.row.col.f32.tf32.tf32.f32 "
        "{%0,%1,%2,%3}, {%4,%5,%6,%7}, {%8,%9}, {%0,%1,%2,%3};\n"
        : "+f"(d[0]), "+f"(d[1]), "+f"(d[2]), "+f"(d[3])
        : "r"(a[0]), "r"(a[1]), "r"(a[2]), "r"(a[3]), "r"(b[0]), "r"(b[1]));
}

// ---------------------------------------------------------------------------
// Kernel 1: QKV projection, out[which] = x[M,E] @ W[E,H], tf32 MMA.
// CTA tile 128(M) x 128(N=HD), BK=32. 8 warps: warp tile 32x64.
// ---------------------------------------------------------------------------
#define XSTR 36     // 36 % 32 == 4  -> A-frag loads conflict-free
#define WSTR 136    // 136 % 32 == 8 -> B-frag loads conflict-free

__global__ __launch_bounds__(256) void qkv_kernel(
    const float* __restrict__ x,
    const float* __restrict__ Wq,
    const float* __restrict__ Wk,
    const float* __restrict__ Wv)
{
    const int which = blockIdx.y;
    const float* __restrict__ W = (which == 0) ? Wq : (which == 1) ? Wk : Wv;
    float* __restrict__ out = (which == 0) ? g_q : (which == 1) ? g_k : g_v;

    __shared__ uint32_t Xs[128 * XSTR];
    __shared__ uint32_t Ws[32 * WSTR];

    const int tid  = threadIdx.x;
    const int warp = tid >> 5;
    const int lane = tid & 31;
    const int g = lane >> 2;
    const int t = lane & 3;
    const int wm = warp & 3;        // 4 M bands of 32
    const int wn = warp >> 2;       // 2 N halves of 64
    const int m0 = wm * 32;
    const int n0 = wn * 64;
    const int row_base = blockIdx.x * 128;

    float acc[2][8][4];
#pragma unroll
    for (int i = 0; i < 2; i++)
#pragma unroll
        for (int j = 0; j < 8; j++)
#pragma unroll
            for (int r = 0; r < 4; r++) acc[i][j][r] = 0.f;

    for (int k0 = 0; k0 < EMB; k0 += 32) {
        // stage X tile 128x32 (1024 float4, 4/thread)
#pragma unroll
        for (int it = 0; it < 4; it++) {
            int idx = tid + it * 256;
            int r = idx >> 3;
            int c = (idx & 7) * 4;
            float4 v = *(const float4*)&x[(size_t)(row_base + r) * EMB + k0 + c];
            uint4 u = make_uint4(f2tf(v.x), f2tf(v.y), f2tf(v.z), f2tf(v.w));
            *(uint4*)&Xs[r * XSTR + c] = u;
        }
        // stage W tile 32x128 (1024 float4, 4/thread)
#pragma unroll
        for (int it = 0; it < 4; it++) {
            int idx = tid + it * 256;
            int r = idx >> 5;
            int c = (idx & 31) * 4;
            float4 v = *(const float4*)&W[(size_t)(k0 + r) * HD + c];
            uint4 u = make_uint4(f2tf(v.x), f2tf(v.y), f2tf(v.z), f2tf(v.w));
            *(uint4*)&Ws[r * WSTR + c] = u;
        }
        __syncthreads();

#pragma unroll
        for (int ks = 0; ks < 4; ks++) {
            const int kk = ks * 8;
            uint32_t a[2][4];
#pragma unroll
            for (int i = 0; i < 2; i++) {
                int ab = (m0 + i * 16 + g) * XSTR + kk + t;
                a[i][0] = Xs[ab];
                a[i][1] = Xs[ab + 8 * XSTR];
                a[i][2] = Xs[ab + 4];
                a[i][3] = Xs[ab + 8 * XSTR + 4];
            }
#pragma unroll
            for (int j = 0; j < 8; j++) {
                int bb = (kk + t) * WSTR + n0 + j * 8 + g;
                uint32_t b[2] = { Ws[bb], Ws[bb + 4 * WSTR] };
                mma8(acc[0][j], a[0], b);
                mma8(acc[1][j], a[1], b);
            }
        }
        __syncthreads();
    }

#pragma unroll
    for (int i = 0; i < 2; i++)
#pragma unroll
        for (int j = 0; j < 8; j++) {
            int row = row_base + m0 + i * 16 + g;
            int col = n0 + j * 8 + 2 * t;
            *(float2*)&out[(size_t)row * HD + col] =
                make_float2(acc[i][j][0], acc[i][j][1]);
            *(float2*)&out[(size_t)(row + 8) * HD + col] =
                make_float2(acc[i][j][2], acc[i][j][3]);
        }
}

// ---------------------------------------------------------------------------
// Kernel 2: causal flash attention, tf32 MMA.
// BM=64 queries, BN=64 keys per iter. 8 warps: warp w owns m16 tile (w&3),
// n-half (w>>2). Softmax stats in registers + small smem exchange per iter.
// ---------------------------------------------------------------------------
#define QKSTR 132   // 132 % 32 == 4 (A-pattern rows: Q, K)
#define VSTR  136   // 136 % 32 == 8 (B-pattern rows: V)
#define PSTR  68    // 68  % 32 == 4 (A-pattern rows: P)

#define ATTN_SMEM_U32 (2 * 64 * QKSTR + 64 * VSTR + 64 * PSTR + 4 * 64)
#define ATTN_SMEM_BYTES (ATTN_SMEM_U32 * 4)

__global__ __launch_bounds__(256) void attn_kernel(float* __restrict__ out)
{
    const int batch = blockIdx.y;
    const int qt = (int)(gridDim.x - 1) - (int)blockIdx.x;   // heavy tiles first
    const int q_base = qt * 64;
    const size_t boff = (size_t)batch * SEQ * HD;

    extern __shared__ uint32_t sm[];
    uint32_t* Qs = sm;                      // 64 x 132
    uint32_t* Ks = Qs + 64 * QKSTR;         // 64 x 132
    uint32_t* Vs = Ks + 64 * QKSTR;         // 64 x 136
    uint32_t* Ps = Vs + 64 * VSTR;          // 64 x 68
    float* redmax = (float*)(Ps + 64 * PSTR);   // [2][64]
    float* redsum = redmax + 2 * 64;            // [2][64]

    const int tid  = threadIdx.x;
    const int warp = tid >> 5;
    const int lane = tid & 31;
    const int g = lane >> 2;
    const int t = lane & 3;
    const int mt = warp & 3;        // m16 tile index
    const int nh = warp >> 2;       // n / hd half
    const int m0 = mt * 16;
    const int nb = nh * 32;         // key-col base for S
    const int hb = nh * 64;         // hd-col base for O
    const int r0l = m0 + g;         // local rows this thread owns
    const int r1l = m0 + g + 8;

    const float qscale = rsqrtf((float)HD);

    // stage Q (scaled, tf32): 64x128 = 2048 float4, 8 per thread
#pragma unroll
    for (int it = 0; it < 8; it++) {
        int idx = tid + it * 256;
        int r = idx >> 5;
        int c = (idx & 31) * 4;
        float4 v = *(const float4*)&g_q[boff + (size_t)(q_base + r) * HD + c];
        uint4 u = make_uint4(f2tf(v.x * qscale), f2tf(v.y * qscale),
                             f2tf(v.z * qscale), f2tf(v.w * qscale));
        *(uint4*)&Qs[r * QKSTR + c] = u;
    }

    float o[8][4];
#pragma unroll
    for (int j = 0; j < 8; j++)
#pragma unroll
        for (int r = 0; r < 4; r++) o[j][r] = 0.f;

    float m_i0 = -1e30f, m_i1 = -1e30f;
    float l_i0 = 0.f,    l_i1 = 0.f;

    for (int kt = 0; kt <= qt; kt++) {
        __syncthreads();    // prior iter's PV reads / Q staging visible

        // stage K, V tiles (tf32): 2 x 2048 float4, 16 per thread
        const int k_base = kt * 64;
#pragma unroll
        for (int it = 0; it < 8; it++) {
            int idx = tid + it * 256;
            int r = idx >> 5;
            int c = (idx & 31) * 4;
            float4 kv = *(const float4*)&g_k[boff + (size_t)(k_base + r) * HD + c];
            *(uint4*)&Ks[r * QKSTR + c] =
                make_uint4(f2tf(kv.x), f2tf(kv.y), f2tf(kv.z), f2tf(kv.w));
            float4 vv = *(const float4*)&g_v[boff + (size_t)(k_base + r) * HD + c];
            *(uint4*)&Vs[r * VSTR + c] =
                make_uint4(f2tf(vv.x), f2tf(vv.y), f2tf(vv.z), f2tf(vv.w));
        }
        __syncthreads();

        // S = Q @ K^T  (warp: 1 m-tile x 4 n-tiles, k=128)
        float s[4][4];
#pragma unroll
        for (int j = 0; j < 4; j++)
#pragma unroll
            for (int r = 0; r < 4; r++) s[j][r] = 0.f;

#pragma unroll
        for (int ks = 0; ks < 16; ks++) {
            const int kk = ks * 8;
            uint32_t a[4];
            int ab = r0l * QKSTR + kk + t;
            a[0] = Qs[ab];
            a[1] = Qs[ab + 8 * QKSTR];
            a[2] = Qs[ab + 4];
            a[3] = Qs[ab + 8 * QKSTR + 4];
#pragma unroll
            for (int j = 0; j < 4; j++) {
                int bb = (nb + j * 8 + g) * QKSTR + kk + t;
                uint32_t b[2] = { Ks[bb], Ks[bb + 4] };
                mma8(s[j], a, b);
            }
        }

        // causal mask on diagonal tile
        if (kt == qt) {
#pragma unroll
            for (int j = 0; j < 4; j++) {
                int cn = nb + j * 8 + 2 * t;
                if (cn     > r0l) s[j][0] = -1e30f;
                if (cn + 1 > r0l) s[j][1] = -1e30f;
                if (cn     > r1l) s[j][2] = -1e30f;
                if (cn + 1 > r1l) s[j][3] = -1e30f;
            }
        }

        // per-half row max -> smem
        float mx0 = -1e30f, mx1 = -1e30f;
#pragma unroll
        for (int j = 0; j < 4; j++) {
            mx0 = fmaxf(mx0, fmaxf(s[j][0], s[j][1]));
            mx1 = fmaxf(mx1, fmaxf(s[j][2], s[j][3]));
        }
        mx0 = fmaxf(mx0, __shfl_xor_sync(0xffffffffu, mx0, 1));
        mx0 = fmaxf(mx0, __shfl_xor_sync(0xffffffffu, mx0, 2));
        mx1 = fmaxf(mx1, __shfl_xor_sync(0xffffffffu, mx1, 1));
        mx1 = fmaxf(mx1, __shfl_xor_sync(0xffffffffu, mx1, 2));
        if (t == 0) {
            redmax[nh * 64 + r0l] = mx0;
            redmax[nh * 64 + r1l] = mx1;
        }
        __syncthreads();

        const float m_new0 = fmaxf(m_i0, fmaxf(redmax[r0l], redmax[64 + r0l]));
        const float m_new1 = fmaxf(m_i1, fmaxf(redmax[r1l], redmax[64 + r1l]));

        // exp, P -> smem (tf32), per-half row sum -> smem
        float sum0 = 0.f, sum1 = 0.f;
#pragma unroll
        for (int j = 0; j < 4; j++) {
            float p00 = __expf(s[j][0] - m_new0);
            float p01 = __expf(s[j][1] - m_new0);
            float p10 = __expf(s[j][2] - m_new1);
            float p11 = __expf(s[j][3] - m_new1);
            sum0 += p00 + p01;
            sum1 += p10 + p11;
            int cn = nb + j * 8 + 2 * t;
            *(uint2*)&Ps[r0l * PSTR + cn] = make_uint2(f2tf(p00), f2tf(p01));
            *(uint2*)&Ps[r1l * PSTR + cn] = make_uint2(f2tf(p10), f2tf(p11));
        }
        sum0 += __shfl_xor_sync(0xffffffffu, sum0, 1);
        sum0 += __shfl_xor_sync(0xffffffffu, sum0, 2);
        sum1 += __shfl_xor_sync(0xffffffffu, sum1, 1);
        sum1 += __shfl_xor_sync(0xffffffffu, sum1, 2);
        if (t == 0) {
            redsum[nh * 64 + r0l] = sum0;
            redsum[nh * 64 + r1l] = sum1;
        }
        __syncthreads();

        const float corr0 = __expf(m_i0 - m_new0);
        const float corr1 = __expf(m_i1 - m_new1);
        l_i0 = l_i0 * corr0 + redsum[r0l] + redsum[64 + r0l];
        l_i1 = l_i1 * corr1 + redsum[r1l] + redsum[64 + r1l];
        m_i0 = m_new0;
        m_i1 = m_new1;

        // rescale O, then O += P @ V
#pragma unroll
        for (int j = 0; j < 8; j++) {
            o[j][0] *= corr0; o[j][1] *= corr0;
            o[j][2] *= corr1; o[j][3] *= corr1;
        }
#pragma unroll
        for (int ks = 0; ks < 8; ks++) {
            const int kk = ks * 8;
            uint32_t a[4];
            int ab = r0l * PSTR + kk + t;
            a[0] = Ps[ab];
            a[1] = Ps[ab + 8 * PSTR];
            a[2] = Ps[ab + 4];
            a[3] = Ps[ab + 8 * PSTR + 4];
#pragma unroll
            for (int j = 0; j < 8; j++) {
                int bb = (kk + t) * VSTR + hb + j * 8 + g;
                uint32_t b[2] = { Vs[bb], Vs[bb + 4 * VSTR] };
                mma8(o[j], a, b);
            }
        }
    }

    // normalize and write
    const float inv0 = 1.f / l_i0;
    const float inv1 = 1.f / l_i1;
#pragma unroll
    for (int j = 0; j < 8; j++) {
        int col = hb + j * 8 + 2 * t;
        int row = q_base + r0l;
        *(float2*)&out[boff + (size_t)row * HD + col] =
            make_float2(o[j][0] * inv0, o[j][1] * inv0);
        *(float2*)&out[boff + (size_t)(row + 8) * HD + col] =
            make_float2(o[j][2] * inv1, o[j][3] * inv1);
    }
}

// ---------------------------------------------------------------------------
extern "C" void kernel_launch(void* const* d_in, const int* in_sizes, int n_in,
                              void* d_out, int out_size)
{
    const float* x  = (const float*)d_in[0];
    const float* Wq = (const float*)d_in[1];
    const float* Wk = (const float*)d_in[2];
    const float* Wv = (const float*)d_in[3];
    float* out = (float*)d_out;

    cudaFuncSetAttribute(attn_kernel,
                         cudaFuncAttributeMaxDynamicSharedMemorySize,
                         ATTN_SMEM_BYTES);

    qkv_kernel<<<dim3(MTOT / 128, 3), 256>>>(x, Wq, Wk, Wv);
    attn_kernel<<<dim3(SEQ / 64, BATCH), 256, ATTN_SMEM_BYTES>>>(out);
}